// round 15
// baseline (speedup 1.0000x reference)
#include <cuda_runtime.h>
#include <math.h>

#define NSEL 1024
#define DD 32
#define KK 128
#define EPSF 1e-5f
#define PI_HALF_F 1.57079632679489661923f

#define TILE 64
#define NTB  (NSEL / TILE)            // 16
#define NOV  (NTB * (NTB + 1) / 2)    // 136 triangular overlap blocks (FIRST)
#define NGW  24                        // G_omega: 3 tiles x 8 n-chunks
#define NC   8                         // C = M^T Omega: 2 l-tiles x 4 n-chunks
#define NGM  4                         // G_m: 4 n-chunks
#define NST  8                         // stats: 8 x 128 rows
#define OFF_GW (NOV)
#define OFF_C  (NOV + NGW)
#define OFF_GM (NOV + NGW + NC)
#define OFF_ST (NOV + NGW + NC + NGM)
#define TOTAL  (OFF_ST + NST)          // 180

#define LHS4 36   // L/H tile row stride (floats)
#define IST  68   // transposed staging i-stride (floats)

// ---- device-global scratch (zero-initialized at load; reset each call) ----
__device__ float g_Gw[KK * KK];
__device__ float g_C[DD * KK];
__device__ float g_Gm[DD * DD];
__device__ float g_sw[KK], g_ubw[KK], g_uaw[KK];
__device__ float g_sm[DD], g_uam[DD], g_ubm[DD];
__device__ double g_sc[8];  // 0:Sa 1:Sa2 2:Sb 3:Sb2 4:Sab 5:overlap 6:exceed 7:shape
__device__ unsigned g_count;

__device__ __forceinline__ float dot4(float4 a, float4 b, float acc) {
    return fmaf(a.x, b.x, fmaf(a.y, b.y, fmaf(a.z, b.z, fmaf(a.w, b.w, acc))));
}

__global__ void __launch_bounds__(512, 2)
fused_kernel(const float* __restrict__ cl, const float* __restrict__ chh,
             const float* __restrict__ pL, const float* __restrict__ pH,
             const float* __restrict__ pR, const float* __restrict__ lr,
             const float* __restrict__ om, const int* __restrict__ idxs,
             float* __restrict__ out) {
    extern __shared__ float smf[];
    __shared__ float sred[3][16];
    __shared__ float sa[128], sb2[128];
    __shared__ float redw[3][4][KK];
    __shared__ float redm[3][4][DD];
    __shared__ double dred[7][16];
    __shared__ int sflag;

    int tx = threadIdx.x, ty = threadIdx.y;   // (16, 32)
    int tid = ty * 16 + tx;
    int b = blockIdx.x;

    // =====================================================================
    if (b < NOV) {
        // ---- overlap (+ diag exceed/shape): 64x64 triangular pair tile ----
        int t = b;
        int by = 0;
        while (t >= NTB - by) { t -= NTB - by; by++; }
        int bx = by + t;
        int i0 = by * TILE, j0 = bx * TILE;
        bool diag = (by == bx);
        float* sLi = smf;
        float* sHi = sLi + TILE * LHS4;
        float* sLj = sHi + TILE * LHS4;
        float* sHj = sLj + TILE * LHS4;
        {   int r = tid >> 3, dq = tid & 7;
            int gi = idxs[i0 + r];
            int gj = idxs[j0 + r];
            ((float4*)&sLi[r * LHS4])[dq] = ((const float4*)cl)[gi * 8 + dq];
            ((float4*)&sHi[r * LHS4])[dq] = ((const float4*)chh)[gi * 8 + dq];
            ((float4*)&sLj[r * LHS4])[dq] = ((const float4*)cl)[gj * 8 + dq];
            ((float4*)&sHj[r * LHS4])[dq] = ((const float4*)chh)[gj * 8 + dq];
        }
        __syncthreads();

        float exc = 0.f, shp = 0.f;
        if (diag) {
#pragma unroll
            for (int p = tid; p < TILE * DD; p += 512) {
                int r = p >> 5, d = p & 31;
                float L = sLi[r * LHS4 + d];
                float H = sHi[r * LHS4 + d];
                float pl = pL[d], ph = pH[d];
                exc += fmaxf(pl - L, 0.f) + fmaxf(H - ph, 0.f)
                     + fmaxf(pl - H, 0.f) + fmaxf(L - ph, 0.f);
                float num = fmaxf((H - L) / pR[d], EPSF);
                float sdiv = num / lr[idxs[i0 + r]];
                sdiv = fminf(fmaxf(sdiv, 0.01f), 1.99f);
                shp += fabsf(tanf((sdiv - 1.0f) * PI_HALF_F));
            }
        }

        float ovacc[2][4] = {{0.f,0.f,0.f,0.f},{0.f,0.f,0.f,0.f}};
#pragma unroll 2
        for (int d = 0; d < DD; d += 4) {
            float4 Li[2], Hi[2], Lj[4], Hj[4];
#pragma unroll
            for (int r = 0; r < 2; r++) {
                Li[r] = *(const float4*)&sLi[(ty + 32 * r) * LHS4 + d];
                Hi[r] = *(const float4*)&sHi[(ty + 32 * r) * LHS4 + d];
            }
#pragma unroll
            for (int c = 0; c < 4; c++) {
                Lj[c] = *(const float4*)&sLj[(tx + 16 * c) * LHS4 + d];
                Hj[c] = *(const float4*)&sHj[(tx + 16 * c) * LHS4 + d];
            }
#pragma unroll
            for (int r = 0; r < 2; r++)
#pragma unroll
                for (int c = 0; c < 4; c++) {
                    ovacc[r][c] += fmaxf(fminf(Hi[r].x, Hj[c].x) - fmaxf(Li[r].x, Lj[c].x), 0.f);
                    ovacc[r][c] += fmaxf(fminf(Hi[r].y, Hj[c].y) - fmaxf(Li[r].y, Lj[c].y), 0.f);
                    ovacc[r][c] += fmaxf(fminf(Hi[r].z, Hj[c].z) - fmaxf(Li[r].z, Lj[c].z), 0.f);
                    ovacc[r][c] += fmaxf(fminf(Hi[r].w, Hj[c].w) - fmaxf(Li[r].w, Lj[c].w), 0.f);
                }
        }
        float s_ov = 0.f;
#pragma unroll
        for (int r = 0; r < 2; r++)
#pragma unroll
            for (int c = 0; c < 4; c++)
                if ((i0 + ty + 32 * r) != (j0 + tx + 16 * c)) s_ov += ovacc[r][c];

#pragma unroll
        for (int off = 16; off > 0; off >>= 1) {
            s_ov += __shfl_xor_sync(0xffffffffu, s_ov, off);
            exc  += __shfl_xor_sync(0xffffffffu, exc,  off);
            shp  += __shfl_xor_sync(0xffffffffu, shp,  off);
        }
        int warp = tid >> 5, lane = tid & 31;
        if (lane == 0) { sred[0][warp] = s_ov; sred[1][warp] = exc; sred[2][warp] = shp; }
        __syncthreads();
        if (tid == 0) {
            float a0 = 0.f, a1 = 0.f, a2 = 0.f;
#pragma unroll
            for (int w = 0; w < 16; w++) { a0 += sred[0][w]; a1 += sred[1][w]; a2 += sred[2][w]; }
            double wgt = diag ? 1.0 : 2.0;
            atomicAdd(&g_sc[5], wgt * (double)a0);
            if (diag) { atomicAdd(&g_sc[6], (double)a1); atomicAdd(&g_sc[7], (double)a2); }
        }

    // =====================================================================
    } else if (b < OFF_C) {
        // ---- G_omega tile: 64x64 output, 128-row slice ----
        int q = b - OFF_GW;
        int t = q >> 3;                       // 0:(0,0) 1:(0,64) 2:(64,64)
        int kt = (t == 2) ? 64 : 0;
        int lt = (t == 0) ? 0 : 64;
        int n0 = (q & 7) * 128;
        float* bufA = smf;
        float* bufB = smf + 64 * IST;
        float acc[2][4] = {{0.f,0.f,0.f,0.f},{0.f,0.f,0.f,0.f}};
        for (int chk = 0; chk < 2; chk++) {
            int base = n0 + chk * 64;
            {   int i = tid & 63, g = tid >> 6;
                const float4* rowp = (const float4*)&om[(base + i) * KK];
#pragma unroll
                for (int v = 0; v < 2; v++) {
                    int c4 = g * 2 + v;
                    float4 xA = rowp[(kt >> 2) + c4];
                    bufA[(c4 * 4 + 0) * IST + i] = xA.x;
                    bufA[(c4 * 4 + 1) * IST + i] = xA.y;
                    bufA[(c4 * 4 + 2) * IST + i] = xA.z;
                    bufA[(c4 * 4 + 3) * IST + i] = xA.w;
                    float4 xB = rowp[(lt >> 2) + c4];
                    bufB[(c4 * 4 + 0) * IST + i] = xB.x;
                    bufB[(c4 * 4 + 1) * IST + i] = xB.y;
                    bufB[(c4 * 4 + 2) * IST + i] = xB.z;
                    bufB[(c4 * 4 + 3) * IST + i] = xB.w;
                }
            }
            __syncthreads();
#pragma unroll 4
            for (int i4 = 0; i4 < 16; i4++) {
                float4 a0 = *(const float4*)&bufA[ty * IST + i4 * 4];
                float4 a1 = *(const float4*)&bufA[(ty + 32) * IST + i4 * 4];
#pragma unroll
                for (int c = 0; c < 4; c++) {
                    float4 bq = *(const float4*)&bufB[(tx + 16 * c) * IST + i4 * 4];
                    acc[0][c] = dot4(a0, bq, acc[0][c]);
                    acc[1][c] = dot4(a1, bq, acc[1][c]);
                }
            }
            __syncthreads();
        }
#pragma unroll
        for (int r = 0; r < 2; r++)
#pragma unroll
            for (int c = 0; c < 4; c++)
                atomicAdd(&g_Gw[(kt + ty + 32 * r) * KK + lt + tx + 16 * c], acc[r][c]);

    // =====================================================================
    } else if (b < OFF_GM) {
        // ---- C = M^T Omega tile: 32x64 output, 256-row slice ----
        int q = b - OFF_C;
        int l0 = (q >> 2) * 64;
        int n0 = (q & 3) * 256;
        float* bufM = smf;
        float* bufW = smf + 32 * IST;
        float accC[4] = {0.f,0.f,0.f,0.f};
        for (int chk = 0; chk < 4; chk++) {
            int base = n0 + chk * 64;
            {   int i = tid & 63, g = tid >> 6;
                const float4* rowp = (const float4*)&om[(base + i) * KK];
#pragma unroll
                for (int v = 0; v < 2; v++) {
                    int c4 = g * 2 + v;
                    float4 x = rowp[(l0 >> 2) + c4];
                    bufW[(c4 * 4 + 0) * IST + i] = x.x;
                    bufW[(c4 * 4 + 1) * IST + i] = x.y;
                    bufW[(c4 * 4 + 2) * IST + i] = x.z;
                    bufW[(c4 * 4 + 3) * IST + i] = x.w;
                }
                int gi = idxs[base + i];
                float4 L = ((const float4*)cl)[gi * 8 + g];
                float4 H = ((const float4*)chh)[gi * 8 + g];
                bufM[(g * 4 + 0) * IST + i] = 0.5f * (L.x + H.x);
                bufM[(g * 4 + 1) * IST + i] = 0.5f * (L.y + H.y);
                bufM[(g * 4 + 2) * IST + i] = 0.5f * (L.z + H.z);
                bufM[(g * 4 + 3) * IST + i] = 0.5f * (L.w + H.w);
            }
            __syncthreads();
#pragma unroll 4
            for (int i4 = 0; i4 < 16; i4++) {
                float4 a = *(const float4*)&bufM[ty * IST + i4 * 4];
#pragma unroll
                for (int c = 0; c < 4; c++) {
                    float4 bq = *(const float4*)&bufW[(tx + 16 * c) * IST + i4 * 4];
                    accC[c] = dot4(a, bq, accC[c]);
                }
            }
            __syncthreads();
        }
#pragma unroll
        for (int c = 0; c < 4; c++)
            atomicAdd(&g_C[ty * KK + l0 + tx + 16 * c], accC[c]);

    // =====================================================================
    } else if (b < OFF_ST) {
        // ---- G_m = M^T M: 32x32 output, 256-row slice ----
        int n0 = (b - OFF_GM) * 256;
        float* bufM = smf;
        float accM[2] = {0.f, 0.f};
        for (int chk = 0; chk < 4; chk++) {
            int base = n0 + chk * 64;
            {   int i = tid & 63, g = tid >> 6;
                int gi = idxs[base + i];
                float4 L = ((const float4*)cl)[gi * 8 + g];
                float4 H = ((const float4*)chh)[gi * 8 + g];
                bufM[(g * 4 + 0) * IST + i] = 0.5f * (L.x + H.x);
                bufM[(g * 4 + 1) * IST + i] = 0.5f * (L.y + H.y);
                bufM[(g * 4 + 2) * IST + i] = 0.5f * (L.z + H.z);
                bufM[(g * 4 + 3) * IST + i] = 0.5f * (L.w + H.w);
            }
            __syncthreads();
#pragma unroll 4
            for (int i4 = 0; i4 < 16; i4++) {
                float4 a = *(const float4*)&bufM[ty * IST + i4 * 4];
#pragma unroll
                for (int c = 0; c < 2; c++) {
                    float4 bq = *(const float4*)&bufM[(tx + 16 * c) * IST + i4 * 4];
                    accM[c] = dot4(a, bq, accM[c]);
                }
            }
            __syncthreads();
        }
#pragma unroll
        for (int c = 0; c < 2; c++)
            atomicAdd(&g_Gm[ty * DD + tx + 16 * c], accM[c]);

    // =====================================================================
    } else {
        // ---- stats over 128 rows ----
        int r0 = (b - OFF_ST) * 128;
        {   int row = tid >> 2, q = tid & 3;
            int gr = r0 + row;
            const float4* wp = (const float4*)&om[gr * KK + q * 32];
            float bp = 0.f;
#pragma unroll
            for (int k = 0; k < 8; k++) { float4 w = wp[k]; bp = dot4(w, w, bp); }
            int gi = idxs[gr];
            float4 L0 = ((const float4*)cl)[gi * 8 + q * 2];
            float4 H0 = ((const float4*)chh)[gi * 8 + q * 2];
            float4 L1 = ((const float4*)cl)[gi * 8 + q * 2 + 1];
            float4 H1 = ((const float4*)chh)[gi * 8 + q * 2 + 1];
            float4 m0, m1;
            m0.x = 0.5f*(L0.x+H0.x); m0.y = 0.5f*(L0.y+H0.y);
            m0.z = 0.5f*(L0.z+H0.z); m0.w = 0.5f*(L0.w+H0.w);
            m1.x = 0.5f*(L1.x+H1.x); m1.y = 0.5f*(L1.y+H1.y);
            m1.z = 0.5f*(L1.z+H1.z); m1.w = 0.5f*(L1.w+H1.w);
            float ap = dot4(m0, m0, dot4(m1, m1, 0.f));
            ap += __shfl_xor_sync(0xffffffffu, ap, 1);
            ap += __shfl_xor_sync(0xffffffffu, ap, 2);
            bp += __shfl_xor_sync(0xffffffffu, bp, 1);
            bp += __shfl_xor_sync(0xffffffffu, bp, 2);
            if (q == 0) { sa[row] = ap; sb2[row] = bp; }
        }
        __syncthreads();
        if (tid < 128) {
            float a = sa[tid], bb = sb2[tid];
            float p[5] = {a, a * a, bb, bb * bb, a * bb};
#pragma unroll
            for (int off = 16; off > 0; off >>= 1)
#pragma unroll
                for (int x = 0; x < 5; x++) p[x] += __shfl_xor_sync(0xffffffffu, p[x], off);
            if ((tid & 31) == 0)
#pragma unroll
                for (int x = 0; x < 5; x++) atomicAdd(&g_sc[x], (double)p[x]);
        }
        {   int k = tid & 127, chn = tid >> 7;
            float s = 0.f, ub = 0.f, ua = 0.f;
#pragma unroll 4
            for (int ii = 0; ii < 32; ii++) {
                int i = chn * 32 + ii;
                float w = om[(r0 + i) * KK + k];
                s += w; ub = fmaf(sb2[i], w, ub); ua = fmaf(sa[i], w, ua);
            }
            redw[0][chn][k] = s; redw[1][chn][k] = ub; redw[2][chn][k] = ua;
        }
        __syncthreads();
        if (tid < 128) {
            float s  = redw[0][0][tid] + redw[0][1][tid] + redw[0][2][tid] + redw[0][3][tid];
            float ub = redw[1][0][tid] + redw[1][1][tid] + redw[1][2][tid] + redw[1][3][tid];
            float ua = redw[2][0][tid] + redw[2][1][tid] + redw[2][2][tid] + redw[2][3][tid];
            atomicAdd(&g_sw[tid], s);
            atomicAdd(&g_ubw[tid], ub);
            atomicAdd(&g_uaw[tid], ua);
        }
        if (tid < 128) {
            int d = tid & 31, chn = tid >> 5;
            float smm = 0.f, uam = 0.f, ubm = 0.f;
#pragma unroll 4
            for (int ii = 0; ii < 32; ii++) {
                int i = chn * 32 + ii;
                int gi = idxs[r0 + i];
                float m = 0.5f * (cl[gi * DD + d] + chh[gi * DD + d]);
                smm += m; uam = fmaf(sa[i], m, uam); ubm = fmaf(sb2[i], m, ubm);
            }
            redm[0][chn][d] = smm; redm[1][chn][d] = uam; redm[2][chn][d] = ubm;
        }
        __syncthreads();
        if (tid < 32) {
            float s0 = redm[0][0][tid] + redm[0][1][tid] + redm[0][2][tid] + redm[0][3][tid];
            float s1 = redm[1][0][tid] + redm[1][1][tid] + redm[1][2][tid] + redm[1][3][tid];
            float s2 = redm[2][0][tid] + redm[2][1][tid] + redm[2][2][tid] + redm[2][3][tid];
            atomicAdd(&g_sm[tid], s0);
            atomicAdd(&g_uam[tid], s1);
            atomicAdd(&g_ubm[tid], s2);
        }
    }

    // ===================== common tail: counter + epilogue ================
    __threadfence();
    if (tid == 0) {
        unsigned prev = atomicAdd(&g_count, 1u);
        sflag = (prev == TOTAL - 1) ? 1 : 0;
    }
    __syncthreads();
    if (sflag) {
        __threadfence();
        double e[7] = {0, 0, 0, 0, 0, 0, 0};
        for (int idx = tid; idx < KK * KK; idx += 512) {
            int k = idx >> 7, l = idx & 127;
            double g = (double)g_Gw[idx];
            e[0] += ((k < 64 && l >= 64) ? 2.0 : 1.0) * g * g;
        }
        for (int idx = tid; idx < DD * KK; idx += 512) { double g = (double)g_C[idx];  e[1] += g * g; }
        for (int idx = tid; idx < DD * DD; idx += 512) { double g = (double)g_Gm[idx]; e[2] += g * g; }
        if (tid < DD) {
            double m = (double)g_sm[tid];
            e[3] = (double)g_uam[tid] * m;
            e[4] = (double)g_ubm[tid] * m;
        }
        if (tid < KK) {
            double s = (double)g_sw[tid];
            e[5] = (double)g_uaw[tid] * s;
            e[6] = (double)g_ubw[tid] * s;
        }
#pragma unroll
        for (int off = 16; off > 0; off >>= 1)
#pragma unroll
            for (int x = 0; x < 7; x++) e[x] += __shfl_xor_sync(0xffffffffu, e[x], off);
        int warp = tid >> 5, lane = tid & 31;
        if (lane == 0)
#pragma unroll
            for (int x = 0; x < 7; x++) dred[x][warp] = e[x];
        __syncthreads();
        if (tid == 0) {
            double f[7];
#pragma unroll
            for (int x = 0; x < 7; x++) {
                double s = 0.0;
#pragma unroll
                for (int w = 0; w < 16; w++) s += dred[x][w];
                f[x] = s;
            }
            double n  = (double)NSEL;
            double Sa = g_sc[0], Sa2 = g_sc[1], Sb = g_sc[2], Sb2 = g_sc[3], Sab = g_sc[4];
            double Sdd = 2.0*n*Sa2 + 2.0*Sa*Sa + 4.0*f[2] - 8.0*f[3];
            double Soo = 2.0*n*Sb2 + 2.0*Sb*Sb + 4.0*f[0] - 8.0*f[6] + n * 1e-10;
            double Sdo = 2.0*n*Sab + 2.0*Sa*Sb + 4.0*f[1] - 4.0*f[5] - 4.0*f[4];
            double ac = fmax(sqrt(Sdd), 1e-5), bc = fmax(sqrt(Soo), 1e-5);
            double q = Sdd/(ac*ac) + Soo/(bc*bc) - 2.0*Sdo/(ac*bc);
            if (q < 0.0) q = 0.0;
            out[0] = (float)(sqrt(q) + g_sc[5] + g_sc[6] + g_sc[7]);
        }
        __syncthreads();
        // reset for the next graph replay
        for (int idx = tid; idx < KK * KK; idx += 512) g_Gw[idx] = 0.f;
        for (int idx = tid; idx < DD * KK; idx += 512) g_C[idx]  = 0.f;
        for (int idx = tid; idx < DD * DD; idx += 512) g_Gm[idx] = 0.f;
        if (tid < KK) { g_sw[tid] = 0.f; g_ubw[tid] = 0.f; g_uaw[tid] = 0.f; }
        if (tid < DD) { g_sm[tid] = 0.f; g_uam[tid] = 0.f; g_ubm[tid] = 0.f; }
        if (tid == 0) {
#pragma unroll
            for (int x = 0; x < 8; x++) g_sc[x] = 0.0;
            g_count = 0u;
        }
    }
}

// ---------------------------------------------------------------------------
extern "C" void kernel_launch(void* const* d_in, const int* in_sizes, int n_in,
                              void* d_out, int out_size) {
    const float* cl  = (const float*)d_in[0];
    const float* chh = (const float*)d_in[1];
    const float* pL  = (const float*)d_in[2];
    const float* pH  = (const float*)d_in[3];
    const float* pR  = (const float*)d_in[4];
    const float* pRg = (const float*)d_in[4];
    const float* lr  = (const float*)d_in[5];
    const float* om  = (const float*)d_in[6];
    const int*  idxs = (const int*)d_in[7];
    float* out = (float*)d_out;
    (void)pRg;

    const int SMEM = 4 * TILE * LHS4 * (int)sizeof(float); // 36864 B (max role)
    cudaFuncSetAttribute(fused_kernel, cudaFuncAttributeMaxDynamicSharedMemorySize, SMEM);

    fused_kernel<<<TOTAL, dim3(16, 32), SMEM>>>(cl, chh, pL, pH, pR, lr, om, idxs, out);
}

// round 16
// speedup vs baseline: 1.0617x; 1.0617x over previous
#include <cuda_runtime.h>
#include <math.h>

#define NSEL 1024
#define DD 32
#define KK 128
#define EPSF 1e-5f
#define PI_HALF_F 1.57079632679489661923f

#define TILE 64
#define NTB  (NSEL / TILE)            // 16
#define NOV  (NTB * (NTB + 1) / 2)    // 136 triangular overlap blocks (FIRST)
#define NGW  24                        // G_omega: 3 tiles x 8 n-chunks
#define NC   8                         // C = M^T Omega
#define NGM  4                         // G_m
#define NST  8                         // stats
#define OFF_GW (NOV)
#define OFF_C  (NOV + NGW)
#define OFF_GM (NOV + NGW + NC)
#define OFF_ST (NOV + NGW + NC + NGM)
#define TOTAL  (OFF_ST + NST)          // 180

#define LHS4 36
#define IST  68

// ---- device-global scratch (zero-initialized at load; reset each call) ----
__device__ float g_Gw[KK * KK];
__device__ float g_C[DD * KK];
__device__ float g_Gm[DD * DD];
__device__ float g_sw[KK], g_ubw[KK], g_uaw[KK];
__device__ float g_sm[DD], g_uam[DD], g_ubm[DD];
__device__ double g_sc[8];  // 0:Sa 1:Sa2 2:Sb 3:Sb2 4:Sab 5:overlap 6:exceed 7:shape
__device__ unsigned g_count;

__device__ __forceinline__ float dot4(float4 a, float4 b, float acc) {
    return fmaf(a.x, b.x, fmaf(a.y, b.y, fmaf(a.z, b.z, fmaf(a.w, b.w, acc))));
}

__global__ void __launch_bounds__(512, 2)
fused_kernel(const float* __restrict__ cl, const float* __restrict__ chh,
             const float* __restrict__ pL, const float* __restrict__ pH,
             const float* __restrict__ pR, const float* __restrict__ lr,
             const float* __restrict__ om, const int* __restrict__ idxs,
             float* __restrict__ out) {
    extern __shared__ float smf[];
    __shared__ float sred[3][16];
    __shared__ float sa[128], sb2[128];
    __shared__ float redw[3][4][KK];
    __shared__ float redm[3][4][DD];
    __shared__ double dred[7][16];
    __shared__ int sflag;

    int tx = threadIdx.x, ty = threadIdx.y;   // (16, 32)
    int tid = ty * 16 + tx;
    int b = blockIdx.x;

    // =====================================================================
    if (b < NOV) {
        // ---- overlap (+ diag exceed/shape): 64x64 triangular pair tile ----
        int t = b;
        int by = 0;
        while (t >= NTB - by) { t -= NTB - by; by++; }
        int bx = by + t;
        int i0 = by * TILE, j0 = bx * TILE;
        bool diag = (by == bx);
        float* sLi = smf;
        float* sHi = sLi + TILE * LHS4;
        float* sLj = sHi + TILE * LHS4;
        float* sHj = sLj + TILE * LHS4;
        {   int r = tid >> 3, dq = tid & 7;
            int gi = idxs[i0 + r];
            int gj = idxs[j0 + r];
            ((float4*)&sLi[r * LHS4])[dq] = ((const float4*)cl)[gi * 8 + dq];
            ((float4*)&sHi[r * LHS4])[dq] = ((const float4*)chh)[gi * 8 + dq];
            ((float4*)&sLj[r * LHS4])[dq] = ((const float4*)cl)[gj * 8 + dq];
            ((float4*)&sHj[r * LHS4])[dq] = ((const float4*)chh)[gj * 8 + dq];
        }
        __syncthreads();

        float exc = 0.f, shp = 0.f;
        if (diag) {
#pragma unroll
            for (int p = tid; p < TILE * DD; p += 512) {
                int r = p >> 5, d = p & 31;
                float L = sLi[r * LHS4 + d];
                float H = sHi[r * LHS4 + d];
                float pl = pL[d], ph = pH[d];
                exc += fmaxf(pl - L, 0.f) + fmaxf(H - ph, 0.f)
                     + fmaxf(pl - H, 0.f) + fmaxf(L - ph, 0.f);
                float num = fmaxf((H - L) / pR[d], EPSF);
                float sdiv = num / lr[idxs[i0 + r]];
                sdiv = fminf(fmaxf(sdiv, 0.01f), 1.99f);
                shp += fabsf(tanf((sdiv - 1.0f) * PI_HALF_F));
            }
        }

        float ovacc[2][4] = {{0.f,0.f,0.f,0.f},{0.f,0.f,0.f,0.f}};
#pragma unroll 2
        for (int d = 0; d < DD; d += 4) {
            float4 Li[2], Hi[2], Lj[4], Hj[4];
#pragma unroll
            for (int r = 0; r < 2; r++) {
                Li[r] = *(const float4*)&sLi[(ty + 32 * r) * LHS4 + d];
                Hi[r] = *(const float4*)&sHi[(ty + 32 * r) * LHS4 + d];
            }
#pragma unroll
            for (int c = 0; c < 4; c++) {
                Lj[c] = *(const float4*)&sLj[(tx + 16 * c) * LHS4 + d];
                Hj[c] = *(const float4*)&sHj[(tx + 16 * c) * LHS4 + d];
            }
#pragma unroll
            for (int r = 0; r < 2; r++)
#pragma unroll
                for (int c = 0; c < 4; c++) {
                    ovacc[r][c] += fmaxf(fminf(Hi[r].x, Hj[c].x) - fmaxf(Li[r].x, Lj[c].x), 0.f);
                    ovacc[r][c] += fmaxf(fminf(Hi[r].y, Hj[c].y) - fmaxf(Li[r].y, Lj[c].y), 0.f);
                    ovacc[r][c] += fmaxf(fminf(Hi[r].z, Hj[c].z) - fmaxf(Li[r].z, Lj[c].z), 0.f);
                    ovacc[r][c] += fmaxf(fminf(Hi[r].w, Hj[c].w) - fmaxf(Li[r].w, Lj[c].w), 0.f);
                }
        }
        float s_ov = 0.f;
#pragma unroll
        for (int r = 0; r < 2; r++)
#pragma unroll
            for (int c = 0; c < 4; c++)
                if ((i0 + ty + 32 * r) != (j0 + tx + 16 * c)) s_ov += ovacc[r][c];

#pragma unroll
        for (int off = 16; off > 0; off >>= 1) {
            s_ov += __shfl_xor_sync(0xffffffffu, s_ov, off);
            exc  += __shfl_xor_sync(0xffffffffu, exc,  off);
            shp  += __shfl_xor_sync(0xffffffffu, shp,  off);
        }
        int warp = tid >> 5, lane = tid & 31;
        if (lane == 0) { sred[0][warp] = s_ov; sred[1][warp] = exc; sred[2][warp] = shp; }
        __syncthreads();
        if (tid == 0) {
            float a0 = 0.f, a1 = 0.f, a2 = 0.f;
#pragma unroll
            for (int w = 0; w < 16; w++) { a0 += sred[0][w]; a1 += sred[1][w]; a2 += sred[2][w]; }
            double wgt = diag ? 1.0 : 2.0;
            atomicAdd(&g_sc[5], wgt * (double)a0);
            if (diag) { atomicAdd(&g_sc[6], (double)a1); atomicAdd(&g_sc[7], (double)a2); }
        }

    // =====================================================================
    } else if (b < OFF_C) {
        // ---- G_omega tile: 64x64 output, 128-row slice ----
        int q = b - OFF_GW;
        int t = q >> 3;                       // 0:(0,0) 1:(0,64) 2:(64,64)
        int kt = (t == 2) ? 64 : 0;
        int lt = (t == 0) ? 0 : 64;
        int n0 = (q & 7) * 128;
        float* bufA = smf;
        float* bufB = smf + 64 * IST;
        float acc[2][4] = {{0.f,0.f,0.f,0.f},{0.f,0.f,0.f,0.f}};
        for (int chk = 0; chk < 2; chk++) {
            int base = n0 + chk * 64;
            {   int i = tid & 63, g = tid >> 6;
                const float4* rowp = (const float4*)&om[(base + i) * KK];
#pragma unroll
                for (int v = 0; v < 2; v++) {
                    int c4 = g * 2 + v;
                    float4 xA = rowp[(kt >> 2) + c4];
                    bufA[(c4 * 4 + 0) * IST + i] = xA.x;
                    bufA[(c4 * 4 + 1) * IST + i] = xA.y;
                    bufA[(c4 * 4 + 2) * IST + i] = xA.z;
                    bufA[(c4 * 4 + 3) * IST + i] = xA.w;
                    float4 xB = rowp[(lt >> 2) + c4];
                    bufB[(c4 * 4 + 0) * IST + i] = xB.x;
                    bufB[(c4 * 4 + 1) * IST + i] = xB.y;
                    bufB[(c4 * 4 + 2) * IST + i] = xB.z;
                    bufB[(c4 * 4 + 3) * IST + i] = xB.w;
                }
            }
            __syncthreads();
#pragma unroll 4
            for (int i4 = 0; i4 < 16; i4++) {
                float4 a0 = *(const float4*)&bufA[ty * IST + i4 * 4];
                float4 a1 = *(const float4*)&bufA[(ty + 32) * IST + i4 * 4];
#pragma unroll
                for (int c = 0; c < 4; c++) {
                    float4 bq = *(const float4*)&bufB[(tx + 16 * c) * IST + i4 * 4];
                    acc[0][c] = dot4(a0, bq, acc[0][c]);
                    acc[1][c] = dot4(a1, bq, acc[1][c]);
                }
            }
            __syncthreads();
        }
#pragma unroll
        for (int r = 0; r < 2; r++)
#pragma unroll
            for (int c = 0; c < 4; c++)
                atomicAdd(&g_Gw[(kt + ty + 32 * r) * KK + lt + tx + 16 * c], acc[r][c]);

    // =====================================================================
    } else if (b < OFF_GM) {
        // ---- C = M^T Omega tile: 32x64 output, 256-row slice ----
        int q = b - OFF_C;
        int l0 = (q >> 2) * 64;
        int n0 = (q & 3) * 256;
        float* bufM = smf;
        float* bufW = smf + 32 * IST;
        float accC[4] = {0.f,0.f,0.f,0.f};
        for (int chk = 0; chk < 4; chk++) {
            int base = n0 + chk * 64;
            {   int i = tid & 63, g = tid >> 6;
                const float4* rowp = (const float4*)&om[(base + i) * KK];
#pragma unroll
                for (int v = 0; v < 2; v++) {
                    int c4 = g * 2 + v;
                    float4 x = rowp[(l0 >> 2) + c4];
                    bufW[(c4 * 4 + 0) * IST + i] = x.x;
                    bufW[(c4 * 4 + 1) * IST + i] = x.y;
                    bufW[(c4 * 4 + 2) * IST + i] = x.z;
                    bufW[(c4 * 4 + 3) * IST + i] = x.w;
                }
                int gi = idxs[base + i];
                float4 L = ((const float4*)cl)[gi * 8 + g];
                float4 H = ((const float4*)chh)[gi * 8 + g];
                bufM[(g * 4 + 0) * IST + i] = 0.5f * (L.x + H.x);
                bufM[(g * 4 + 1) * IST + i] = 0.5f * (L.y + H.y);
                bufM[(g * 4 + 2) * IST + i] = 0.5f * (L.z + H.z);
                bufM[(g * 4 + 3) * IST + i] = 0.5f * (L.w + H.w);
            }
            __syncthreads();
#pragma unroll 4
            for (int i4 = 0; i4 < 16; i4++) {
                float4 a = *(const float4*)&bufM[ty * IST + i4 * 4];
#pragma unroll
                for (int c = 0; c < 4; c++) {
                    float4 bq = *(const float4*)&bufW[(tx + 16 * c) * IST + i4 * 4];
                    accC[c] = dot4(a, bq, accC[c]);
                }
            }
            __syncthreads();
        }
#pragma unroll
        for (int c = 0; c < 4; c++)
            atomicAdd(&g_C[ty * KK + l0 + tx + 16 * c], accC[c]);

    // =====================================================================
    } else if (b < OFF_ST) {
        // ---- G_m = M^T M: 32x32 output, 256-row slice ----
        int n0 = (b - OFF_GM) * 256;
        float* bufM = smf;
        float accM[2] = {0.f, 0.f};
        for (int chk = 0; chk < 4; chk++) {
            int base = n0 + chk * 64;
            {   int i = tid & 63, g = tid >> 6;
                int gi = idxs[base + i];
                float4 L = ((const float4*)cl)[gi * 8 + g];
                float4 H = ((const float4*)chh)[gi * 8 + g];
                bufM[(g * 4 + 0) * IST + i] = 0.5f * (L.x + H.x);
                bufM[(g * 4 + 1) * IST + i] = 0.5f * (L.y + H.y);
                bufM[(g * 4 + 2) * IST + i] = 0.5f * (L.z + H.z);
                bufM[(g * 4 + 3) * IST + i] = 0.5f * (L.w + H.w);
            }
            __syncthreads();
#pragma unroll 4
            for (int i4 = 0; i4 < 16; i4++) {
                float4 a = *(const float4*)&bufM[ty * IST + i4 * 4];
#pragma unroll
                for (int c = 0; c < 2; c++) {
                    float4 bq = *(const float4*)&bufM[(tx + 16 * c) * IST + i4 * 4];
                    accM[c] = dot4(a, bq, accM[c]);
                }
            }
            __syncthreads();
        }
#pragma unroll
        for (int c = 0; c < 2; c++)
            atomicAdd(&g_Gm[ty * DD + tx + 16 * c], accM[c]);

    // =====================================================================
    } else {
        // ---- stats over 128 rows ----
        int r0 = (b - OFF_ST) * 128;
        {   int row = tid >> 2, q = tid & 3;
            int gr = r0 + row;
            const float4* wp = (const float4*)&om[gr * KK + q * 32];
            float bp = 0.f;
#pragma unroll
            for (int k = 0; k < 8; k++) { float4 w = wp[k]; bp = dot4(w, w, bp); }
            int gi = idxs[gr];
            float4 L0 = ((const float4*)cl)[gi * 8 + q * 2];
            float4 H0 = ((const float4*)chh)[gi * 8 + q * 2];
            float4 L1 = ((const float4*)cl)[gi * 8 + q * 2 + 1];
            float4 H1 = ((const float4*)chh)[gi * 8 + q * 2 + 1];
            float4 m0, m1;
            m0.x = 0.5f*(L0.x+H0.x); m0.y = 0.5f*(L0.y+H0.y);
            m0.z = 0.5f*(L0.z+H0.z); m0.w = 0.5f*(L0.w+H0.w);
            m1.x = 0.5f*(L1.x+H1.x); m1.y = 0.5f*(L1.y+H1.y);
            m1.z = 0.5f*(L1.z+H1.z); m1.w = 0.5f*(L1.w+H1.w);
            float ap = dot4(m0, m0, dot4(m1, m1, 0.f));
            ap += __shfl_xor_sync(0xffffffffu, ap, 1);
            ap += __shfl_xor_sync(0xffffffffu, ap, 2);
            bp += __shfl_xor_sync(0xffffffffu, bp, 1);
            bp += __shfl_xor_sync(0xffffffffu, bp, 2);
            if (q == 0) { sa[row] = ap; sb2[row] = bp; }
        }
        __syncthreads();
        if (tid < 128) {
            float a = sa[tid], bb = sb2[tid];
            float p[5] = {a, a * a, bb, bb * bb, a * bb};
#pragma unroll
            for (int off = 16; off > 0; off >>= 1)
#pragma unroll
                for (int x = 0; x < 5; x++) p[x] += __shfl_xor_sync(0xffffffffu, p[x], off);
            if ((tid & 31) == 0)
#pragma unroll
                for (int x = 0; x < 5; x++) atomicAdd(&g_sc[x], (double)p[x]);
        }
        {   int k = tid & 127, chn = tid >> 7;
            float s = 0.f, ub = 0.f, ua = 0.f;
#pragma unroll 4
            for (int ii = 0; ii < 32; ii++) {
                int i = chn * 32 + ii;
                float w = om[(r0 + i) * KK + k];
                s += w; ub = fmaf(sb2[i], w, ub); ua = fmaf(sa[i], w, ua);
            }
            redw[0][chn][k] = s; redw[1][chn][k] = ub; redw[2][chn][k] = ua;
        }
        __syncthreads();
        if (tid < 128) {
            float s  = redw[0][0][tid] + redw[0][1][tid] + redw[0][2][tid] + redw[0][3][tid];
            float ub = redw[1][0][tid] + redw[1][1][tid] + redw[1][2][tid] + redw[1][3][tid];
            float ua = redw[2][0][tid] + redw[2][1][tid] + redw[2][2][tid] + redw[2][3][tid];
            atomicAdd(&g_sw[tid], s);
            atomicAdd(&g_ubw[tid], ub);
            atomicAdd(&g_uaw[tid], ua);
        }
        if (tid < 128) {
            int d = tid & 31, chn = tid >> 5;
            float smm = 0.f, uam = 0.f, ubm = 0.f;
#pragma unroll 4
            for (int ii = 0; ii < 32; ii++) {
                int i = chn * 32 + ii;
                int gi = idxs[r0 + i];
                float m = 0.5f * (cl[gi * DD + d] + chh[gi * DD + d]);
                smm += m; uam = fmaf(sa[i], m, uam); ubm = fmaf(sb2[i], m, ubm);
            }
            redm[0][chn][d] = smm; redm[1][chn][d] = uam; redm[2][chn][d] = ubm;
        }
        __syncthreads();
        if (tid < 32) {
            float s0 = redm[0][0][tid] + redm[0][1][tid] + redm[0][2][tid] + redm[0][3][tid];
            float s1 = redm[1][0][tid] + redm[1][1][tid] + redm[1][2][tid] + redm[1][3][tid];
            float s2 = redm[2][0][tid] + redm[2][1][tid] + redm[2][2][tid] + redm[2][3][tid];
            atomicAdd(&g_sm[tid], s0);
            atomicAdd(&g_uam[tid], s1);
            atomicAdd(&g_ubm[tid], s2);
        }
    }

    // ===================== common tail: counter + epilogue ================
    // NOTE: gpu-scope fence executed by tid 0 ONLY — an all-thread
    // __threadfence() emits CCTL.IVALL (L1 flush) per thread and was the
    // R14/R15 serialization bug. The cumulative fence after __syncthreads()
    // covers the other threads' atomics.
    __syncthreads();
    if (tid == 0) {
        __threadfence();
        unsigned prev = atomicAdd(&g_count, 1u);
        sflag = (prev == TOTAL - 1) ? 1 : 0;
    }
    __syncthreads();
    if (sflag) {
        if (tid == 0) __threadfence();
        __syncthreads();
        double e[7] = {0, 0, 0, 0, 0, 0, 0};
        for (int idx = tid; idx < KK * KK; idx += 512) {
            int k = idx >> 7, l = idx & 127;
            double g = (double)g_Gw[idx];
            e[0] += ((k < 64 && l >= 64) ? 2.0 : 1.0) * g * g;
        }
        for (int idx = tid; idx < DD * KK; idx += 512) { double g = (double)g_C[idx];  e[1] += g * g; }
        for (int idx = tid; idx < DD * DD; idx += 512) { double g = (double)g_Gm[idx]; e[2] += g * g; }
        if (tid < DD) {
            double m = (double)g_sm[tid];
            e[3] = (double)g_uam[tid] * m;
            e[4] = (double)g_ubm[tid] * m;
        }
        if (tid < KK) {
            double s = (double)g_sw[tid];
            e[5] = (double)g_uaw[tid] * s;
            e[6] = (double)g_ubw[tid] * s;
        }
#pragma unroll
        for (int off = 16; off > 0; off >>= 1)
#pragma unroll
            for (int x = 0; x < 7; x++) e[x] += __shfl_xor_sync(0xffffffffu, e[x], off);
        int warp = tid >> 5, lane = tid & 31;
        if (lane == 0)
#pragma unroll
            for (int x = 0; x < 7; x++) dred[x][warp] = e[x];
        __syncthreads();
        if (tid == 0) {
            double f[7];
#pragma unroll
            for (int x = 0; x < 7; x++) {
                double s = 0.0;
#pragma unroll
                for (int w = 0; w < 16; w++) s += dred[x][w];
                f[x] = s;
            }
            double n  = (double)NSEL;
            double Sa = g_sc[0], Sa2 = g_sc[1], Sb = g_sc[2], Sb2 = g_sc[3], Sab = g_sc[4];
            double Sdd = 2.0*n*Sa2 + 2.0*Sa*Sa + 4.0*f[2] - 8.0*f[3];
            double Soo = 2.0*n*Sb2 + 2.0*Sb*Sb + 4.0*f[0] - 8.0*f[6] + n * 1e-10;
            double Sdo = 2.0*n*Sab + 2.0*Sa*Sb + 4.0*f[1] - 4.0*f[5] - 4.0*f[4];
            double ac = fmax(sqrt(Sdd), 1e-5), bc = fmax(sqrt(Soo), 1e-5);
            double q = Sdd/(ac*ac) + Soo/(bc*bc) - 2.0*Sdo/(ac*bc);
            if (q < 0.0) q = 0.0;
            out[0] = (float)(sqrt(q) + g_sc[5] + g_sc[6] + g_sc[7]);
        }
        __syncthreads();
        // reset for the next graph replay
        for (int idx = tid; idx < KK * KK; idx += 512) g_Gw[idx] = 0.f;
        for (int idx = tid; idx < DD * KK; idx += 512) g_C[idx]  = 0.f;
        for (int idx = tid; idx < DD * DD; idx += 512) g_Gm[idx] = 0.f;
        if (tid < KK) { g_sw[tid] = 0.f; g_ubw[tid] = 0.f; g_uaw[tid] = 0.f; }
        if (tid < DD) { g_sm[tid] = 0.f; g_uam[tid] = 0.f; g_ubm[tid] = 0.f; }
        if (tid == 0) {
#pragma unroll
            for (int x = 0; x < 8; x++) g_sc[x] = 0.0;
            g_count = 0u;
        }
    }
}

// ---------------------------------------------------------------------------
extern "C" void kernel_launch(void* const* d_in, const int* in_sizes, int n_in,
                              void* d_out, int out_size) {
    const float* cl  = (const float*)d_in[0];
    const float* chh = (const float*)d_in[1];
    const float* pL  = (const float*)d_in[2];
    const float* pH  = (const float*)d_in[3];
    const float* pR  = (const float*)d_in[4];
    const float* lr  = (const float*)d_in[5];
    const float* om  = (const float*)d_in[6];
    const int*  idxs = (const int*)d_in[7];
    float* out = (float*)d_out;

    const int SMEM = 4 * TILE * LHS4 * (int)sizeof(float); // 36864 B (max role)
    cudaFuncSetAttribute(fused_kernel, cudaFuncAttributeMaxDynamicSharedMemorySize, SMEM);

    fused_kernel<<<TOTAL, dim3(16, 32), SMEM>>>(cl, chh, pL, pH, pR, lr, om, idxs, out);
}

// round 17
// speedup vs baseline: 2.1717x; 2.0456x over previous
#include <cuda_runtime.h>
#include <math.h>

#define NSEL 1024
#define DD 32
#define KK 128
#define EPSF 1e-5f
#define PI_HALF_F 1.57079632679489661923f

#define TILE 64
#define NTB  (NSEL / TILE)            // 16
#define NBLK (NTB * (NTB + 1) / 2)    // 136 triangular blocks, one wave
#define NTHR 1024
#define LHS4 36   // fp32 tile row stride (floats): 144B, %128=16 -> conflict-free
#define WS2  68   // omega row stride in bf162 units: 272B, %128=16 -> conflict-free

// ---- global accumulators (zero at load; reset by last block each call) ----
__device__ double g_acc[6];     // 0:S_dd 1:S_oo 2:S_do 3:overlap 4:exceed 5:shape
__device__ unsigned g_count;

__device__ __forceinline__ float dot4(float4 a, float4 b, float acc) {
    return fmaf(a.x, b.x, fmaf(a.y, b.y, fmaf(a.z, b.z, fmaf(a.w, b.w, acc))));
}
__device__ __forceinline__ unsigned bf2pack(float hi, float lo) {
    unsigned r;
    asm("cvt.rn.bf16x2.f32 %0, %1, %2;" : "=r"(r) : "f"(hi), "f"(lo));
    return r;
}
__device__ __forceinline__ unsigned hfma2(unsigned a, unsigned b, unsigned c) {
    unsigned d;
    asm("fma.rn.bf16x2 %0, %1, %2, %3;" : "=r"(d) : "r"(a), "r"(b), "r"(c));
    return d;
}
__device__ __forceinline__ float bf2sum(unsigned p) {
    return __uint_as_float(p << 16) + __uint_as_float(p & 0xffff0000u);
}

// ---------------------------------------------------------------------------
// 136 triangular 64x64 pair tiles, 1024 threads (16x64) -> 8 warps/SMSP,
// 1x4 microtile: i-row {ty}, j-cols {tx+16c}. Omega tiles in bf16x2.
__global__ void __launch_bounds__(NTHR, 1)
pair_kernel(const float* __restrict__ cl, const float* __restrict__ chh,
            const float* __restrict__ pL, const float* __restrict__ pH,
            const float* __restrict__ pR, const float* __restrict__ lr,
            const float* __restrict__ om, const int* __restrict__ idxs,
            float* __restrict__ out) {
    extern __shared__ float smf[];
    float* sLi = smf;                       // 64*36
    float* sHi = sLi + TILE * LHS4;
    float* sLj = sHi + TILE * LHS4;
    float* sHj = sLj + TILE * LHS4;
    float* sMi = sHj + TILE * LHS4;
    float* sMj = sMi + TILE * LHS4;
    unsigned* sWi = (unsigned*)(sMj + TILE * LHS4);   // 64*68 u32 (bf162)
    unsigned* sWj = sWi + TILE * WS2;
    __shared__ float sIpI[TILE], sIpJ[TILE], sRmI[TILE], sRmJ[TILE];
    __shared__ float bred[6][32];

    int tx = threadIdx.x, ty = threadIdx.y;   // (16, 64)
    int tid = ty * 16 + tx;

    // triangular block decode (by <= bx)
    int t = blockIdx.x;
    int by = 0;
    while (t >= NTB - by) { t -= NTB - by; by++; }
    int bx = by + t;
    int i0 = by * TILE, j0 = bx * TILE;
    bool diag = (by == bx);

    // ---- gather L/H + mid tiles (512 float4 slots) ----
    if (tid < 512) {
        int r = tid >> 3, dq = tid & 7;
        int gi = idxs[i0 + r];
        int gj = idxs[j0 + r];
        float4 Lf = ((const float4*)cl)[gi * 8 + dq];
        float4 Hf = ((const float4*)chh)[gi * 8 + dq];
        ((float4*)&sLi[r * LHS4])[dq] = Lf;
        ((float4*)&sHi[r * LHS4])[dq] = Hf;
        float4 Mf;
        Mf.x = 0.5f * (Lf.x + Hf.x); Mf.y = 0.5f * (Lf.y + Hf.y);
        Mf.z = 0.5f * (Lf.z + Hf.z); Mf.w = 0.5f * (Lf.w + Hf.w);
        ((float4*)&sMi[r * LHS4])[dq] = Mf;

        Lf = ((const float4*)cl)[gj * 8 + dq];
        Hf = ((const float4*)chh)[gj * 8 + dq];
        ((float4*)&sLj[r * LHS4])[dq] = Lf;
        ((float4*)&sHj[r * LHS4])[dq] = Hf;
        Mf.x = 0.5f * (Lf.x + Hf.x); Mf.y = 0.5f * (Lf.y + Hf.y);
        Mf.z = 0.5f * (Lf.z + Hf.z); Mf.w = 0.5f * (Lf.w + Hf.w);
        ((float4*)&sMj[r * LHS4])[dq] = Mf;
    }
    // ---- omega tiles: fp32 gmem -> bf16x2 smem (2048 slots) ----
#pragma unroll
    for (int p = tid; p < TILE * (KK / 4); p += NTHR) {
        int r = p >> 5, kq = p & 31;
        float4 x = ((const float4*)om)[(i0 + r) * 32 + kq];
        *(uint2*)&sWi[r * WS2 + kq * 2] =
            make_uint2(bf2pack(x.y, x.x), bf2pack(x.w, x.z));
        x = ((const float4*)om)[(j0 + r) * 32 + kq];
        *(uint2*)&sWj[r * WS2 + kq * 2] =
            make_uint2(bf2pack(x.y, x.x), bf2pack(x.w, x.z));
    }
    __syncthreads();

    // ---- per-row ||omega||^2 (fp32 from gmem, 16 thr/row) and ||mid||^2 ----
    {
        int row = tid >> 4, q = tid & 15;   // row == ty, q == tx
        const float4* wi = (const float4*)&om[(i0 + row) * KK] + q * 2;
        const float4* wj = (const float4*)&om[(j0 + row) * KK] + q * 2;
        float pi = dot4(wi[0], wi[0], dot4(wi[1], wi[1], 0.f));
        float pj = dot4(wj[0], wj[0], dot4(wj[1], wj[1], 0.f));
        float mi = 0.f, mj = 0.f;
        if (q < 8) {
            float4 a = ((const float4*)&sMi[row * LHS4])[q];
            float4 b = ((const float4*)&sMj[row * LHS4])[q];
            mi = dot4(a, a, 0.f);
            mj = dot4(b, b, 0.f);
        }
#pragma unroll
        for (int off = 1; off < 16; off <<= 1) {
            pi += __shfl_xor_sync(0xffffffffu, pi, off);
            pj += __shfl_xor_sync(0xffffffffu, pj, off);
            mi += __shfl_xor_sync(0xffffffffu, mi, off);
            mj += __shfl_xor_sync(0xffffffffu, mj, off);
        }
        if (q == 0) { sIpI[row] = pi; sIpJ[row] = pj; sRmI[row] = mi; sRmJ[row] = mj; }
    }

    // ---- exceed + shape: diagonal blocks only ----
    float exc = 0.f, shp = 0.f;
    if (diag) {
#pragma unroll
        for (int p = tid; p < TILE * DD; p += NTHR) {
            int r = p >> 5, d = p & 31;
            float L = sLi[r * LHS4 + d];
            float H = sHi[r * LHS4 + d];
            float pl = pL[d], ph = pH[d];
            exc += fmaxf(pl - L, 0.f) + fmaxf(H - ph, 0.f)
                 + fmaxf(pl - H, 0.f) + fmaxf(L - ph, 0.f);
            float num = fmaxf((H - L) / pR[d], EPSF);
            float sdiv = num / lr[idxs[i0 + r]];
            sdiv = fminf(fmaxf(sdiv, 0.01f), 1.99f);
            shp += fabsf(tanf((sdiv - 1.0f) * PI_HALF_F));
        }
    }
    __syncthreads();

    // microtile: i-row ty, j-cols {tx+16c}
    const unsigned* wiB = &sWi[ty * WS2];
    const unsigned* wjB0 = &sWj[tx * WS2];
    const unsigned* wjB1 = &sWj[(tx + 16) * WS2];
    const unsigned* wjB2 = &sWj[(tx + 32) * WS2];
    const unsigned* wjB3 = &sWj[(tx + 48) * WS2];

    // ---- omega dot products: bf16x2 FMAs (16 chunks of 8 k) ----
    unsigned dp[4] = {0u, 0u, 0u, 0u};
#pragma unroll 4
    for (int k8 = 0; k8 < 16; k8++) {
        uint4 a = *(const uint4*)(wiB + k8 * 4);
        uint4 b0 = *(const uint4*)(wjB0 + k8 * 4);
        uint4 b1 = *(const uint4*)(wjB1 + k8 * 4);
        uint4 b2 = *(const uint4*)(wjB2 + k8 * 4);
        uint4 b3 = *(const uint4*)(wjB3 + k8 * 4);
        dp[0] = hfma2(a.x, b0.x, dp[0]); dp[0] = hfma2(a.y, b0.y, dp[0]);
        dp[0] = hfma2(a.z, b0.z, dp[0]); dp[0] = hfma2(a.w, b0.w, dp[0]);
        dp[1] = hfma2(a.x, b1.x, dp[1]); dp[1] = hfma2(a.y, b1.y, dp[1]);
        dp[1] = hfma2(a.z, b1.z, dp[1]); dp[1] = hfma2(a.w, b1.w, dp[1]);
        dp[2] = hfma2(a.x, b2.x, dp[2]); dp[2] = hfma2(a.y, b2.y, dp[2]);
        dp[2] = hfma2(a.z, b2.z, dp[2]); dp[2] = hfma2(a.w, b2.w, dp[2]);
        dp[3] = hfma2(a.x, b3.x, dp[3]); dp[3] = hfma2(a.y, b3.y, dp[3]);
        dp[3] = hfma2(a.z, b3.z, dp[3]); dp[3] = hfma2(a.w, b3.w, dp[3]);
    }
    float dot[4];
#pragma unroll
    for (int c = 0; c < 4; c++) dot[c] = bf2sum(dp[c]);

    // ---- mid dot products (fp32, d=32) ----
    float md[4] = {0.f, 0.f, 0.f, 0.f};
#pragma unroll 2
    for (int d4 = 0; d4 < 8; d4++) {
        float4 a = *(const float4*)&sMi[ty * LHS4 + d4 * 4];
        md[0] = dot4(a, *(const float4*)&sMj[tx * LHS4 + d4 * 4], md[0]);
        md[1] = dot4(a, *(const float4*)&sMj[(tx + 16) * LHS4 + d4 * 4], md[1]);
        md[2] = dot4(a, *(const float4*)&sMj[(tx + 32) * LHS4 + d4 * 4], md[2]);
        md[3] = dot4(a, *(const float4*)&sMj[(tx + 48) * LHS4 + d4 * 4], md[3]);
    }

    // ---- overlap-only box loop (direct accumulation, 4 partials) ----
    float sova[4] = {0.f, 0.f, 0.f, 0.f};
#pragma unroll 2
    for (int d4 = 0; d4 < 8; d4++) {
        float4 Li = *(const float4*)&sLi[ty * LHS4 + d4 * 4];
        float4 Hi = *(const float4*)&sHi[ty * LHS4 + d4 * 4];
#pragma unroll
        for (int c = 0; c < 4; c++) {
            float4 Lj = *(const float4*)&sLj[(tx + 16 * c) * LHS4 + d4 * 4];
            float4 Hj = *(const float4*)&sHj[(tx + 16 * c) * LHS4 + d4 * 4];
            sova[c] += fmaxf(fminf(Hi.x, Hj.x) - fmaxf(Li.x, Lj.x), 0.f);
            sova[c] += fmaxf(fminf(Hi.y, Hj.y) - fmaxf(Li.y, Lj.y), 0.f);
            sova[c] += fmaxf(fminf(Hi.z, Hj.z) - fmaxf(Li.z, Lj.z), 0.f);
            sova[c] += fmaxf(fminf(Hi.w, Hj.w) - fmaxf(Li.w, Lj.w), 0.f);
        }
    }
    float s_ov = (sova[0] + sova[1]) + (sova[2] + sova[3]);
    // cancel the self-pair (i==j) contribution on diagonal blocks exactly
    if (diag && ((ty - tx) & 15) == 0) {
        float wsum = 0.f;
#pragma unroll
        for (int d = 0; d < DD; d++)
            wsum += fmaxf(sHi[ty * LHS4 + d] - sLi[ty * LHS4 + d], 0.f);
        s_ov -= wsum;
    }

    // ---- combine: distance partials ----
    float ipi = sIpI[ty], rmi = sRmI[ty];
    float s_dd = 0.f, s_oo = 0.f, s_do = 0.f;
#pragma unroll
    for (int c = 0; c < 4; c++) {
        float ipj = sIpJ[tx + 16 * c], rmj = sRmJ[tx + 16 * c];
        float d2v = fmaf(-2.f, md[c], rmi + rmj);            // ||mi-mj||^2
        float oDv = fmaxf(fmaf(-2.f, dot[c], ipi + ipj), EPSF);
        s_dd = fmaf(d2v, d2v, s_dd);
        s_oo = fmaf(oDv, oDv, s_oo);
        s_do = fmaf(d2v, oDv, s_do);
    }

    // ---- block reduction ----
#pragma unroll
    for (int off = 16; off > 0; off >>= 1) {
        s_dd += __shfl_xor_sync(0xffffffffu, s_dd, off);
        s_oo += __shfl_xor_sync(0xffffffffu, s_oo, off);
        s_do += __shfl_xor_sync(0xffffffffu, s_do, off);
        s_ov += __shfl_xor_sync(0xffffffffu, s_ov, off);
        exc  += __shfl_xor_sync(0xffffffffu, exc,  off);
        shp  += __shfl_xor_sync(0xffffffffu, shp,  off);
    }
    int warp = tid >> 5, lane = tid & 31;
    if (lane == 0) {
        bred[0][warp] = s_dd; bred[1][warp] = s_oo; bred[2][warp] = s_do;
        bred[3][warp] = s_ov; bred[4][warp] = exc;  bred[5][warp] = shp;
    }
    __syncthreads();
    if (tid == 0) {
        float a0 = 0.f, a1 = 0.f, a2 = 0.f, a3 = 0.f, a4 = 0.f, a5 = 0.f;
#pragma unroll
        for (int w = 0; w < 32; w++) {
            a0 += bred[0][w]; a1 += bred[1][w]; a2 += bred[2][w];
            a3 += bred[3][w]; a4 += bred[4][w]; a5 += bred[5][w];
        }
        double wgt = diag ? 1.0 : 2.0;   // symmetry: off-diagonal tiles count twice
        atomicAdd(&g_acc[0], wgt * (double)a0);
        atomicAdd(&g_acc[1], wgt * (double)a1);
        atomicAdd(&g_acc[2], wgt * (double)a2);
        atomicAdd(&g_acc[3], wgt * (double)a3);
        if (diag) {
            atomicAdd(&g_acc[4], (double)a4);
            atomicAdd(&g_acc[5], (double)a5);
        }

        __threadfence();
        unsigned prev = atomicAdd(&g_count, 1u);
        if (prev == NBLK - 1) {
            __threadfence();
            double S_dd = g_acc[0], S_oo = g_acc[1], S_do = g_acc[2];
            double a = sqrt(S_dd), b = sqrt(S_oo);
            double ac = fmax(a, 1e-5), bc = fmax(b, 1e-5);
            double q = S_dd / (ac * ac) + S_oo / (bc * bc) - 2.0 * S_do / (ac * bc);
            if (q < 0.0) q = 0.0;
            out[0] = (float)(sqrt(q) + g_acc[3] + g_acc[4] + g_acc[5]);
            // reset for the next graph replay
            g_acc[0] = 0.0; g_acc[1] = 0.0; g_acc[2] = 0.0;
            g_acc[3] = 0.0; g_acc[4] = 0.0; g_acc[5] = 0.0;
            g_count = 0u;
        }
    }
}

// ---------------------------------------------------------------------------
extern "C" void kernel_launch(void* const* d_in, const int* in_sizes, int n_in,
                              void* d_out, int out_size) {
    const float* cl  = (const float*)d_in[0];  // childrenLower  [4096,32]
    const float* chh = (const float*)d_in[1];  // childrenHigher [4096,32]
    const float* pL  = (const float*)d_in[2];  // parentL_ [32]
    const float* pH  = (const float*)d_in[3];  // parentH_ [32]
    const float* pR  = (const float*)d_in[4];  // parentRange [32]
    const float* lr  = (const float*)d_in[5];  // leavesRatio [4096]
    const float* om  = (const float*)d_in[6];  // omegaEmb [1024,128]
    const int*  idxs = (const int*)d_in[7];    // idIndexes [1024]
    float* out = (float*)d_out;

    // 6 fp32 tiles (64x36) + 2 bf162 tiles (64x68 u32) = 90112 B
    const int SMEM = (6 * TILE * LHS4 + 2 * TILE * WS2) * (int)sizeof(float);
    cudaFuncSetAttribute(pair_kernel, cudaFuncAttributeMaxDynamicSharedMemorySize, SMEM);

    pair_kernel<<<NBLK, dim3(16, 64), SMEM>>>(cl, chh, pL, pH, pR, lr, om, idxs, out);
}